// round 13
// baseline (speedup 1.0000x reference)
#include <cuda_runtime.h>

typedef unsigned long long ull;

#define NT   200000
#define NL   50000
#define DD   128
#define ETA  1000000
#define EREV 1000000
#define ELL  500000
#define ELBL 500000

#define CAP_TA  64
#define CAP_LL  64
#define CAP_REV 32

#define NB_ACC   ((NL + 7) / 8)        // 6250 accum blocks (8 warps = 8 rows each)
#define NB_TL    ((NL + 127) / 128)    // 391 blocks per label-sized GEMM
#define NB_TT    ((NT + 127) / 128)    // 1563 blocks for title-sized GEMM
#define NB_FILL  ((ETA + ELL + EREV + 255) / 256)

// ---------------- scratch (device globals: no allocation allowed) ----------------
__device__ float g_agg_ta [(size_t)NL * DD];   // 25.6 MB
__device__ float g_yl     [(size_t)NL * DD];   // 25.6 MB  (YL = x_label @ W_l_tl^T)
__device__ float g_zl     [(size_t)NL * DD];   // 25.6 MB  (ZL = x_label @ W_l_ll^T)
__device__ int   g_cnt_rev[NT];
__device__ int   g_cnt_ta [NL];
__device__ int   g_cnt_ll [NL];
__device__ int   g_bkt_ta [(size_t)NL * CAP_TA];
__device__ int   g_bkt_ll [(size_t)NL * CAP_LL];
__device__ int   g_bkt_rev[(size_t)NT * CAP_REV];
__device__ int2  g_ovf_ta [ETA];               // capacity = E: always correct
__device__ int2  g_ovf_ll [ELL];
__device__ int2  g_ovf_rev[EREV];
__device__ int   g_ovf_n[3];                   // [0]=ta [1]=ll [2]=rev
__device__ float g_Wsum[DD * DD];
__device__ float g_bsum[DD];

// ---------------- packed f32x2 helpers (Blackwell FFMA2 path) ----------------
__device__ __forceinline__ ull pack2(float x, float y) {
    ull r; asm("mov.b64 %0, {%1, %2};" : "=l"(r) : "f"(x), "f"(y)); return r;
}
__device__ __forceinline__ void unpack2(float& x, float& y, ull v) {
    asm("mov.b64 {%0, %1}, %2;" : "=f"(x), "=f"(y) : "l"(v));
}
__device__ __forceinline__ void ffma2(ull& acc, ull a, ull b) {
    asm("fma.rn.f32x2 %0, %1, %2, %0;" : "+l"(acc) : "l"(a), "l"(b));
}

// ---------------- setup: zero counters + fold weights (one launch) ----------------
__global__ void setup_kernel(const float* __restrict__ wr1, const float* __restrict__ wr2,
                             const float* __restrict__ b1,  const float* __restrict__ b2) {
    int tid    = blockIdx.x * blockDim.x + threadIdx.x;
    int stride = gridDim.x * blockDim.x;
    for (int i = tid; i < NT; i += stride) g_cnt_rev[i] = 0;
    for (int i = tid; i < NL; i += stride) { g_cnt_ta[i] = 0; g_cnt_ll[i] = 0; }
    for (int i = tid; i < DD * DD; i += stride) g_Wsum[i] = wr1[i] + wr2[i];
    if (tid < DD) g_bsum[tid] = b1[tid] + b2[tid];
    if (tid < 3)  g_ovf_n[tid] = 0;
}

// ---------------- bucket fill ----------------
__device__ __forceinline__ void fill_one(
    int e, const int* __restrict__ src, const int* __restrict__ dst,
    int* __restrict__ cnt, int* __restrict__ bkt, int cap,
    int2* __restrict__ ovf, int* __restrict__ ovfn)
{
    int s = src[e];
    int d = dst[e];
    int pos = atomicAdd(&cnt[d], 1);
    if (pos < cap) {
        bkt[(size_t)d * cap + pos] = s;
    } else {
        int o = atomicAdd(ovfn, 1);
        ovf[o] = make_int2(s, d);
    }
}

__global__ void __launch_bounds__(256) fill_all_kernel(
    const int* __restrict__ ta_src,  const int* __restrict__ ta_dst,
    const int* __restrict__ ll_src,  const int* __restrict__ ll_dst,
    const int* __restrict__ rev_src, const int* __restrict__ rev_dst)
{
    int i = blockIdx.x * blockDim.x + threadIdx.x;
    if (i < ETA) {
        fill_one(i, ta_src, ta_dst, g_cnt_ta, g_bkt_ta, CAP_TA, g_ovf_ta, &g_ovf_n[0]);
    } else if (i < ETA + ELL) {
        fill_one(i - ETA, ll_src, ll_dst, g_cnt_ll, g_bkt_ll, CAP_LL, g_ovf_ll, &g_ovf_n[1]);
    } else if (i < ETA + ELL + EREV) {
        fill_one(i - ETA - ELL, rev_src, rev_dst, g_cnt_rev, g_bkt_rev, CAP_REV, g_ovf_rev, &g_ovf_n[2]);
    }
}

// ---------------- accumulate block body (1 warp per destination row) ----------------
__device__ __forceinline__ void accum_block(
    int bid, const float* __restrict__ x, const int* __restrict__ bkt,
    const int* __restrict__ cnt, int cap, float* __restrict__ agg, int N)
{
    int w    = bid * 8 + (threadIdx.x >> 5);
    int lane = threadIdx.x & 31;
    if (w >= N) return;
    int c = cnt[w];
    if (c > cap) c = cap;
    const int* b = bkt + (size_t)w * cap;
    float4 acc = make_float4(0.f, 0.f, 0.f, 0.f);
    int i = 0;
    for (; i + 4 <= c; i += 4) {
        int s0 = b[i], s1 = b[i + 1], s2 = b[i + 2], s3 = b[i + 3];
        float4 v0 = *((const float4*)(x + (size_t)s0 * DD) + lane);
        float4 v1 = *((const float4*)(x + (size_t)s1 * DD) + lane);
        float4 v2 = *((const float4*)(x + (size_t)s2 * DD) + lane);
        float4 v3 = *((const float4*)(x + (size_t)s3 * DD) + lane);
        acc.x += v0.x + v1.x + v2.x + v3.x;
        acc.y += v0.y + v1.y + v2.y + v3.y;
        acc.z += v0.z + v1.z + v2.z + v3.z;
        acc.w += v0.w + v1.w + v2.w + v3.w;
    }
    for (; i < c; i++) {
        int s = b[i];
        float4 v = *((const float4*)(x + (size_t)s * DD) + lane);
        acc.x += v.x; acc.y += v.y; acc.z += v.z; acc.w += v.w;
    }
    *((float4*)(agg + (size_t)w * DD) + lane) = acc;
}

// ---------------- GEMM block body: 128 rows x 128 cols, thread = 16 rows x 4 cols ----------------
struct MatArg { const float* A; const float* W; const int* cnt; };

#define AT_STRIDE 130   // 128 + 2 pad; *4B = 520, 8B-aligned for ull LDS

template <int NM, bool RELU, bool GATHER>
__device__ __forceinline__ void gemm_block(
    int bid, MatArg m0, MatArg m1,
    const float* __restrict__ bias,
    const float* __restrict__ gY, const int* __restrict__ gbkt,
    const int* __restrict__ gcnt, int gcap,
    const int2* __restrict__ govf, const int* __restrict__ govfn,
    float* __restrict__ out, int nrows,
    float* sAT, float (*sW)[DD])
{
    const int t    = threadIdx.x;
    const int tx   = t & 31;
    const int ty   = t >> 5;
    const int row0 = bid * 128;
    const int col  = tx * 4;

    ull acc2[8][4];   // [row-pair][col]
    {
        float4 b = bias ? *(const float4*)(bias + col) : make_float4(0.f, 0.f, 0.f, 0.f);
        ull b0 = pack2(b.x, b.x), b1 = pack2(b.y, b.y);
        ull b2 = pack2(b.z, b.z), b3 = pack2(b.w, b.w);
        #pragma unroll
        for (int p = 0; p < 8; p++) {
            acc2[p][0] = b0; acc2[p][1] = b1; acc2[p][2] = b2; acc2[p][3] = b3;
        }
    }

    MatArg mats[2] = { m0, m1 };
    #pragma unroll
    for (int m = 0; m < NM; m++) {
        const float* __restrict__ A   = mats[m].A;
        const float* __restrict__ W   = mats[m].W;
        const int*   __restrict__ cnt = mats[m].cnt;
        for (int kc = 0; kc < 4; kc++) {
            __syncthreads();
            // --- load A tile (128 rows x 32 k), scaled, stored TRANSPOSED: sAT[k][row] ---
            #pragma unroll
            for (int i = 0; i < 4; i++) {
                int lin = (t + i * 256) * 4;
                int r   = lin >> 5;          // 0..127
                int kk  = lin & 31;
                int gr  = row0 + r;
                float4 v = make_float4(0.f, 0.f, 0.f, 0.f);
                float  s = 1.0f;
                if (gr < nrows) {
                    v = *(const float4*)(A + (size_t)gr * DD + kc * 32 + kk);
                    if (cnt) s = 1.0f / fmaxf((float)cnt[gr], 1.0f);
                }
                sAT[(kk + 0) * AT_STRIDE + r] = v.x * s;
                sAT[(kk + 1) * AT_STRIDE + r] = v.y * s;
                sAT[(kk + 2) * AT_STRIDE + r] = v.z * s;
                sAT[(kk + 3) * AT_STRIDE + r] = v.w * s;
            }
            // --- load W tile transposed: sW[k][col] ---
            {
                int c = t & 127, half = t >> 7;
                const float* Wp = W + c * DD + kc * 32 + half * 16;
                #pragma unroll
                for (int q = 0; q < 4; q++) {
                    float4 w = *(const float4*)(Wp + q * 4);
                    int kk = half * 16 + q * 4;
                    sW[kk + 0][c] = w.x; sW[kk + 1][c] = w.y;
                    sW[kk + 2][c] = w.z; sW[kk + 3][c] = w.w;
                }
            }
            __syncthreads();
            // --- inner product: 32 k-steps, 32 FFMA2 each ---
            #pragma unroll 2
            for (int k = 0; k < 32; k++) {
                const float* ap = &sAT[k * AT_STRIDE + ty * 16];
                ull a[8];
                #pragma unroll
                for (int j = 0; j < 8; j++) a[j] = *(const ull*)(ap + 2 * j);
                float4 w = *(const float4*)&sW[k][col];
                ull w0 = pack2(w.x, w.x);
                ull w1 = pack2(w.y, w.y);
                ull w2 = pack2(w.z, w.z);
                ull w3 = pack2(w.w, w.w);
                #pragma unroll
                for (int p = 0; p < 8; p++) {
                    ffma2(acc2[p][0], a[p], w0);
                    ffma2(acc2[p][1], a[p], w1);
                    ffma2(acc2[p][2], a[p], w2);
                    ffma2(acc2[p][3], a[p], w3);
                }
            }
        }
    }

    // epilogue: unpack, optional bucket-gather mean-add (warp-uniform row loop), relu, store
    #pragma unroll
    for (int p = 0; p < 8; p++) {
        int rlo = row0 + ty * 16 + 2 * p;
        float4 o2[2];
        unpack2(o2[0].x, o2[1].x, acc2[p][0]);
        unpack2(o2[0].y, o2[1].y, acc2[p][1]);
        unpack2(o2[0].z, o2[1].z, acc2[p][2]);
        unpack2(o2[0].w, o2[1].w, acc2[p][3]);
        #pragma unroll
        for (int h = 0; h < 2; h++) {
            int r = rlo + h;
            if (r >= nrows) continue;
            float4 o = o2[h];
            if (GATHER) {
                int c  = gcnt[r];
                int cc = c < gcap ? c : gcap;
                const int* b = gbkt + (size_t)r * gcap;
                float4 add = make_float4(0.f, 0.f, 0.f, 0.f);
                for (int i = 0; i < cc; i++) {
                    int s = b[i];
                    float4 v = *(const float4*)(gY + (size_t)s * DD + col);
                    add.x += v.x; add.y += v.y; add.z += v.z; add.w += v.w;
                }
                int novf = *govfn;
                if (novf > 0) {          // ~never taken; exact fallback
                    for (int i = 0; i < novf; i++) {
                        int2 e = govf[i];
                        if (e.y == r) {
                            float4 v = *(const float4*)(gY + (size_t)e.x * DD + col);
                            add.x += v.x; add.y += v.y; add.z += v.z; add.w += v.w;
                        }
                    }
                }
                float sc = 1.0f / fmaxf((float)c, 1.0f);
                o.x += add.x * sc; o.y += add.y * sc;
                o.z += add.z * sc; o.w += add.w * sc;
            }
            if (RELU) {
                o.x = fmaxf(o.x, 0.f); o.y = fmaxf(o.y, 0.f);
                o.z = fmaxf(o.z, 0.f); o.w = fmaxf(o.w, 0.f);
            }
            *(float4*)(out + (size_t)r * DD + col) = o;
        }
    }
}

// ---------------- kernel A: accum_ta + YL transform + ZL transform (co-launched) ----------------
__global__ void __launch_bounds__(256, 2) midA_kernel(
    const float* __restrict__ x_title, const float* __restrict__ label_embed,
    const float* __restrict__ W_l_tl,  const float* __restrict__ W_l_ll)
{
    __shared__ __align__(16) float sAT[32 * AT_STRIDE];
    __shared__ __align__(16) float sW[32][DD];
    int b = blockIdx.x;
    MatArg dummy { nullptr, nullptr, nullptr };
    if (b < NB_ACC) {
        accum_block(b, x_title, g_bkt_ta, g_cnt_ta, CAP_TA, g_agg_ta, NL);
    } else if (b < NB_ACC + NB_TL) {
        MatArg y0 { label_embed, W_l_tl, nullptr };
        gemm_block<1, false, false>(b - NB_ACC, y0, dummy, nullptr,
            nullptr, nullptr, nullptr, 0, nullptr, nullptr, g_yl, NL, sAT, sW);
    } else {
        MatArg z0 { label_embed, W_l_ll, nullptr };
        gemm_block<1, false, false>(b - NB_ACC - NB_TL, z0, dummy, nullptr,
            nullptr, nullptr, nullptr, 0, nullptr, nullptr, g_zl, NL, sAT, sW);
    }
}

// ---------------- ta overflow cleanup (expected ~0 entries) ----------------
__global__ void __launch_bounds__(256) overflow_ta_kernel(const float* __restrict__ x)
{
    int w      = (int)((blockIdx.x * blockDim.x + threadIdx.x) >> 5);
    int nwarps = (int)((gridDim.x * blockDim.x) >> 5);
    int lane   = threadIdx.x & 31;
    int n = g_ovf_n[0];
    for (int idx = w; idx < n; idx += nwarps) {
        int2 e = g_ovf_ta[idx];
        float4 v = *((const float4*)(x + (size_t)e.x * DD) + lane);
        float* a = g_agg_ta + (size_t)e.y * DD + lane * 4;
        atomicAdd(a + 0, v.x);
        atomicAdd(a + 1, v.y);
        atomicAdd(a + 2, v.z);
        atomicAdd(a + 3, v.w);
    }
}

// ---------------- kernel B: out_title GEMM + out_label GEMM (co-launched) ----------------
__global__ void __launch_bounds__(256, 2) midB_kernel(
    const float* __restrict__ x_title, const float* __restrict__ label_embed,
    const float* __restrict__ W_r_tl,  const float* __restrict__ W_l_tl,
    const float* __restrict__ b_l_tl,
    float* __restrict__ out_title, float* __restrict__ out_label)
{
    __shared__ __align__(16) float sAT[32 * AT_STRIDE];
    __shared__ __align__(16) float sW[32][DD];
    int b = blockIdx.x;
    MatArg dummy { nullptr, nullptr, nullptr };
    if (b < NB_TT) {
        // out_title = relu( x_title @ W_r_tl^T + b_l_tl + mean over rev-bucket of YL rows )
        MatArg t0 { x_title, W_r_tl, nullptr };
        gemm_block<1, true, true>(b, t0, dummy, b_l_tl,
            g_yl, g_bkt_rev, g_cnt_rev, CAP_REV, g_ovf_rev, &g_ovf_n[2],
            out_title, NT, sAT, sW);
    } else {
        // out_label = relu( agg_ta/cnt @ W_l_tl^T + x_label @ Wsum^T + bsum
        //                   + mean over ll-bucket of ZL rows )
        MatArg l0 { g_agg_ta, W_l_tl, g_cnt_ta };
        MatArg l1 { label_embed, g_Wsum, nullptr };
        gemm_block<2, true, true>(b - NB_TT, l0, l1, g_bsum,
            g_zl, g_bkt_ll, g_cnt_ll, CAP_LL, g_ovf_ll, &g_ovf_n[1],
            out_label, NL, sAT, sW);
    }
}

// ---------------- supervision-edge dot products: one warp per edge ----------------
__global__ void __launch_bounds__(256) pred_kernel(
    const float* __restrict__ ot, const float* __restrict__ ol,
    const int* __restrict__ es, const int* __restrict__ ed,
    float* __restrict__ pred, int E)
{
    int e    = (int)(((size_t)blockIdx.x * blockDim.x + threadIdx.x) >> 5);
    int lane = threadIdx.x & 31;
    if (e >= E) return;
    int s = es[e], d = ed[e];
    float4 a = *((const float4*)(ot + (size_t)s * DD) + lane);
    float4 b = *((const float4*)(ol + (size_t)d * DD) + lane);
    float v = a.x * b.x + a.y * b.y + a.z * b.z + a.w * b.w;
    #pragma unroll
    for (int o = 16; o > 0; o >>= 1) v += __shfl_xor_sync(0xffffffffu, v, o);
    if (lane == 0) pred[e] = v;
}

// ---------------- orchestration ----------------
extern "C" void kernel_launch(void* const* d_in, const int* in_sizes, int n_in,
                              void* d_out, int out_size)
{
    const float* x_title      = (const float*)d_in[0];
    const float* label_embed  = (const float*)d_in[1];   // == x_label (label_node_id is identity)
    const float* W_l_tl       = (const float*)d_in[2];
    const float* b_l_tl       = (const float*)d_in[3];
    const float* W_r_tl       = (const float*)d_in[4];
    const float* W_l_ll       = (const float*)d_in[5];
    const float* b_l_ll       = (const float*)d_in[6];
    const float* W_r_ll       = (const float*)d_in[7];
    const int* ta_src   = (const int*)d_in[9];
    const int* ta_dst   = (const int*)d_in[10];
    const int* rev_src  = (const int*)d_in[11];
    const int* rev_dst  = (const int*)d_in[12];
    const int* ll_src   = (const int*)d_in[13];
    const int* ll_dst   = (const int*)d_in[14];
    const int* el_src   = (const int*)d_in[15];
    const int* el_dst   = (const int*)d_in[16];

    float* out       = (float*)d_out;
    float* pred      = out;                                   // [ELBL]
    float* out_title = out + ELBL;                            // [NT, D]
    float* out_label = out + ELBL + (size_t)NT * DD;          // [NL, D]

    // setup: zero counters + fold Wsum/bsum
    setup_kernel<<<512, 256>>>(W_r_tl, W_r_ll, b_l_tl, b_l_ll);

    // pass 1: all bucket fills (one launch, 3 independent relations)
    fill_all_kernel<<<NB_FILL, 256>>>(
        ta_src, ta_dst, ll_src, ll_dst, rev_src, rev_dst);

    // kernel A: accum_ta (L2-bound) + YL + ZL transforms (FMA-bound), co-resident
    midA_kernel<<<NB_ACC + 2 * NB_TL, 256>>>(x_title, label_embed, W_l_tl, W_l_ll);

    // ta overflow cleanup (expected empty; exactness guarantee)
    overflow_ta_kernel<<<64, 256>>>(x_title);

    // kernel B: both output GEMMs with fused epilogue gathers
    midB_kernel<<<NB_TT + NB_TL, 256>>>(
        x_title, label_embed, W_r_tl, W_l_tl, b_l_tl, out_title, out_label);

    // supervision-edge dot products
    pred_kernel<<<(int)(((size_t)ELBL * 32 + 255) / 256), 256>>>(
        out_title, out_label, el_src, el_dst, pred, ELBL);
}

// round 14
// speedup vs baseline: 1.0937x; 1.0937x over previous
#include <cuda_runtime.h>

typedef unsigned long long ull;

#define NT   200000
#define NL   50000
#define DD   128
#define ETA  1000000
#define EREV 1000000
#define ELL  500000
#define ELBL 500000

#define CAP_TA  64
#define CAP_LL  64
#define CAP_REV 32

#define NB_ACC   ((NL + 7) / 8)        // 6250 accum blocks (8 warps = 8 rows each)
#define NB_TL    ((NL + 63) / 64)      // 782 blocks per label-sized GEMM
#define NB_TT    ((NT + 63) / 64)      // 3125 blocks for title-sized GEMM
#define NB_FILL  ((ETA + ELL + EREV + 255) / 256)

// ---------------- scratch (device globals: no allocation allowed) ----------------
__device__ float g_agg_ta [(size_t)NL * DD];   // 25.6 MB
__device__ float g_yl     [(size_t)NL * DD];   // 25.6 MB  (YL = x_label @ W_l_tl^T)
__device__ float g_zl     [(size_t)NL * DD];   // 25.6 MB  (ZL = x_label @ W_l_ll^T)
__device__ int   g_cnt_rev[NT];
__device__ int   g_cnt_ta [NL];
__device__ int   g_cnt_ll [NL];
__device__ int   g_bkt_ta [(size_t)NL * CAP_TA];
__device__ int   g_bkt_ll [(size_t)NL * CAP_LL];
__device__ int   g_bkt_rev[(size_t)NT * CAP_REV];
__device__ int2  g_ovf_ta [ETA];               // capacity = E: always correct
__device__ int2  g_ovf_ll [ELL];
__device__ int2  g_ovf_rev[EREV];
__device__ int   g_ovf_n[3];                   // [0]=ta [1]=ll [2]=rev
__device__ float g_Wsum[DD * DD];
__device__ float g_bsum[DD];

// ---------------- packed f32x2 helpers (Blackwell FFMA2 path) ----------------
__device__ __forceinline__ ull pack2(float x, float y) {
    ull r; asm("mov.b64 %0, {%1, %2};" : "=l"(r) : "f"(x), "f"(y)); return r;
}
__device__ __forceinline__ void unpack2(float& x, float& y, ull v) {
    asm("mov.b64 {%0, %1}, %2;" : "=f"(x), "=f"(y) : "l"(v));
}
__device__ __forceinline__ void ffma2(ull& acc, ull a, ull b) {
    asm("fma.rn.f32x2 %0, %1, %2, %0;" : "+l"(acc) : "l"(a), "l"(b));
}

// ---------------- setup: zero counters + fold weights (one launch) ----------------
__global__ void setup_kernel(const float* __restrict__ wr1, const float* __restrict__ wr2,
                             const float* __restrict__ b1,  const float* __restrict__ b2) {
    int tid    = blockIdx.x * blockDim.x + threadIdx.x;
    int stride = gridDim.x * blockDim.x;
    for (int i = tid; i < NT; i += stride) g_cnt_rev[i] = 0;
    for (int i = tid; i < NL; i += stride) { g_cnt_ta[i] = 0; g_cnt_ll[i] = 0; }
    for (int i = tid; i < DD * DD; i += stride) g_Wsum[i] = wr1[i] + wr2[i];
    if (tid < DD) g_bsum[tid] = b1[tid] + b2[tid];
    if (tid < 3)  g_ovf_n[tid] = 0;
}

// ---------------- bucket fill ----------------
__device__ __forceinline__ void fill_one(
    int e, const int* __restrict__ src, const int* __restrict__ dst,
    int* __restrict__ cnt, int* __restrict__ bkt, int cap,
    int2* __restrict__ ovf, int* __restrict__ ovfn)
{
    int s = src[e];
    int d = dst[e];
    int pos = atomicAdd(&cnt[d], 1);
    if (pos < cap) {
        bkt[(size_t)d * cap + pos] = s;
    } else {
        int o = atomicAdd(ovfn, 1);
        ovf[o] = make_int2(s, d);
    }
}

__global__ void __launch_bounds__(256) fill_all_kernel(
    const int* __restrict__ ta_src,  const int* __restrict__ ta_dst,
    const int* __restrict__ ll_src,  const int* __restrict__ ll_dst,
    const int* __restrict__ rev_src, const int* __restrict__ rev_dst)
{
    int i = blockIdx.x * blockDim.x + threadIdx.x;
    if (i < ETA) {
        fill_one(i, ta_src, ta_dst, g_cnt_ta, g_bkt_ta, CAP_TA, g_ovf_ta, &g_ovf_n[0]);
    } else if (i < ETA + ELL) {
        fill_one(i - ETA, ll_src, ll_dst, g_cnt_ll, g_bkt_ll, CAP_LL, g_ovf_ll, &g_ovf_n[1]);
    } else if (i < ETA + ELL + EREV) {
        fill_one(i - ETA - ELL, rev_src, rev_dst, g_cnt_rev, g_bkt_rev, CAP_REV, g_ovf_rev, &g_ovf_n[2]);
    }
}

// ---------------- accumulate block body (1 warp per destination row) ----------------
__device__ __forceinline__ void accum_block(
    int bid, const float* __restrict__ x, const int* __restrict__ bkt,
    const int* __restrict__ cnt, int cap, float* __restrict__ agg, int N)
{
    int w    = bid * 8 + (threadIdx.x >> 5);
    int lane = threadIdx.x & 31;
    if (w >= N) return;
    int c = cnt[w];
    if (c > cap) c = cap;
    const int* b = bkt + (size_t)w * cap;
    float4 acc = make_float4(0.f, 0.f, 0.f, 0.f);
    int i = 0;
    for (; i + 4 <= c; i += 4) {
        int s0 = b[i], s1 = b[i + 1], s2 = b[i + 2], s3 = b[i + 3];
        float4 v0 = *((const float4*)(x + (size_t)s0 * DD) + lane);
        float4 v1 = *((const float4*)(x + (size_t)s1 * DD) + lane);
        float4 v2 = *((const float4*)(x + (size_t)s2 * DD) + lane);
        float4 v3 = *((const float4*)(x + (size_t)s3 * DD) + lane);
        acc.x += v0.x + v1.x + v2.x + v3.x;
        acc.y += v0.y + v1.y + v2.y + v3.y;
        acc.z += v0.z + v1.z + v2.z + v3.z;
        acc.w += v0.w + v1.w + v2.w + v3.w;
    }
    for (; i < c; i++) {
        int s = b[i];
        float4 v = *((const float4*)(x + (size_t)s * DD) + lane);
        acc.x += v.x; acc.y += v.y; acc.z += v.z; acc.w += v.w;
    }
    *((float4*)(agg + (size_t)w * DD) + lane) = acc;
}

// ---------------- GEMM block body (FFMA2 core + optional epilogue bucket-gather) ----------------
struct MatArg { const float* A; const float* W; const int* cnt; };

#define AT_STRIDE 66

template <int NM, bool RELU, bool GATHER>
__device__ __forceinline__ void gemm_block(
    int bid, MatArg m0, MatArg m1,
    const float* __restrict__ bias,
    const float* __restrict__ gY, const int* __restrict__ gbkt,
    const int* __restrict__ gcnt, int gcap,
    const int2* __restrict__ govf, const int* __restrict__ govfn,
    float* __restrict__ out, int nrows,
    float* sAT, float (*sW)[DD])
{
    const int t    = threadIdx.x;
    const int tx   = t & 31;
    const int ty   = t >> 5;
    const int row0 = bid * 64;
    const int col  = tx * 4;

    ull acc2[4][4];   // [row-pair][col]
    {
        float4 b = bias ? *(const float4*)(bias + col) : make_float4(0.f, 0.f, 0.f, 0.f);
        ull b0 = pack2(b.x, b.x), b1 = pack2(b.y, b.y);
        ull b2 = pack2(b.z, b.z), b3 = pack2(b.w, b.w);
        #pragma unroll
        for (int p = 0; p < 4; p++) {
            acc2[p][0] = b0; acc2[p][1] = b1; acc2[p][2] = b2; acc2[p][3] = b3;
        }
    }

    MatArg mats[2] = { m0, m1 };
    #pragma unroll
    for (int m = 0; m < NM; m++) {
        const float* __restrict__ A   = mats[m].A;
        const float* __restrict__ W   = mats[m].W;
        const int*   __restrict__ cnt = mats[m].cnt;
        for (int kc = 0; kc < 4; kc++) {
            __syncthreads();
            // --- load A tile, scaled, stored TRANSPOSED: sAT[k][row] ---
            #pragma unroll
            for (int i = 0; i < 2; i++) {
                int lin = (t + i * 256) * 4;
                int r   = lin >> 5;          // 0..63
                int kk  = lin & 31;
                int gr  = row0 + r;
                float4 v = make_float4(0.f, 0.f, 0.f, 0.f);
                float  s = 1.0f;
                if (gr < nrows) {
                    v = *(const float4*)(A + (size_t)gr * DD + kc * 32 + kk);
                    if (cnt) s = 1.0f / fmaxf((float)cnt[gr], 1.0f);
                }
                sAT[(kk + 0) * AT_STRIDE + r] = v.x * s;
                sAT[(kk + 1) * AT_STRIDE + r] = v.y * s;
                sAT[(kk + 2) * AT_STRIDE + r] = v.z * s;
                sAT[(kk + 3) * AT_STRIDE + r] = v.w * s;
            }
            // --- load W tile transposed: sW[k][col] ---
            {
                int c = t & 127, half = t >> 7;
                const float* Wp = W + c * DD + kc * 32 + half * 16;
                #pragma unroll
                for (int q = 0; q < 4; q++) {
                    float4 w = *(const float4*)(Wp + q * 4);
                    int kk = half * 16 + q * 4;
                    sW[kk + 0][c] = w.x; sW[kk + 1][c] = w.y;
                    sW[kk + 2][c] = w.z; sW[kk + 3][c] = w.w;
                }
            }
            __syncthreads();
            // --- inner product: 32 k-steps, 16 FFMA2 each ---
            #pragma unroll 4
            for (int k = 0; k < 32; k++) {
                const float* ap = &sAT[k * AT_STRIDE + ty * 8];
                ull a01 = *(const ull*)(ap + 0);
                ull a23 = *(const ull*)(ap + 2);
                ull a45 = *(const ull*)(ap + 4);
                ull a67 = *(const ull*)(ap + 6);
                float4 w = *(const float4*)&sW[k][col];
                ull w0 = pack2(w.x, w.x);
                ull w1 = pack2(w.y, w.y);
                ull w2 = pack2(w.z, w.z);
                ull w3 = pack2(w.w, w.w);
                ffma2(acc2[0][0], a01, w0); ffma2(acc2[0][1], a01, w1);
                ffma2(acc2[0][2], a01, w2); ffma2(acc2[0][3], a01, w3);
                ffma2(acc2[1][0], a23, w0); ffma2(acc2[1][1], a23, w1);
                ffma2(acc2[1][2], a23, w2); ffma2(acc2[1][3], a23, w3);
                ffma2(acc2[2][0], a45, w0); ffma2(acc2[2][1], a45, w1);
                ffma2(acc2[2][2], a45, w2); ffma2(acc2[2][3], a45, w3);
                ffma2(acc2[3][0], a67, w0); ffma2(acc2[3][1], a67, w1);
                ffma2(acc2[3][2], a67, w2); ffma2(acc2[3][3], a67, w3);
            }
        }
    }

    // epilogue: unpack, optional bucket-gather mean-add (warp-uniform row loop), relu, store
    #pragma unroll
    for (int p = 0; p < 4; p++) {
        int rlo = row0 + ty * 8 + 2 * p;
        float4 o2[2];
        unpack2(o2[0].x, o2[1].x, acc2[p][0]);
        unpack2(o2[0].y, o2[1].y, acc2[p][1]);
        unpack2(o2[0].z, o2[1].z, acc2[p][2]);
        unpack2(o2[0].w, o2[1].w, acc2[p][3]);
        #pragma unroll
        for (int h = 0; h < 2; h++) {
            int r = rlo + h;
            if (r >= nrows) continue;
            float4 o = o2[h];
            if (GATHER) {
                int c  = gcnt[r];
                int cc = c < gcap ? c : gcap;
                const int* b = gbkt + (size_t)r * gcap;
                float4 add = make_float4(0.f, 0.f, 0.f, 0.f);
                for (int i = 0; i < cc; i++) {
                    int s = b[i];
                    float4 v = *(const float4*)(gY + (size_t)s * DD + col);
                    add.x += v.x; add.y += v.y; add.z += v.z; add.w += v.w;
                }
                int novf = *govfn;
                if (novf > 0) {          // ~never taken; exact fallback
                    for (int i = 0; i < novf; i++) {
                        int2 e = govf[i];
                        if (e.y == r) {
                            float4 v = *(const float4*)(gY + (size_t)e.x * DD + col);
                            add.x += v.x; add.y += v.y; add.z += v.z; add.w += v.w;
                        }
                    }
                }
                float sc = 1.0f / fmaxf((float)c, 1.0f);
                o.x += add.x * sc; o.y += add.y * sc;
                o.z += add.z * sc; o.w += add.w * sc;
            }
            if (RELU) {
                o.x = fmaxf(o.x, 0.f); o.y = fmaxf(o.y, 0.f);
                o.z = fmaxf(o.z, 0.f); o.w = fmaxf(o.w, 0.f);
            }
            *(float4*)(out + (size_t)r * DD + col) = o;
        }
    }
}

// ---------------- kernel A: accum_ta + YL transform + ZL transform (co-launched) ----------------
__global__ void __launch_bounds__(256) midA_kernel(
    const float* __restrict__ x_title, const float* __restrict__ label_embed,
    const float* __restrict__ W_l_tl,  const float* __restrict__ W_l_ll)
{
    __shared__ __align__(16) float sAT[32 * AT_STRIDE];
    __shared__ __align__(16) float sW[32][DD];
    int b = blockIdx.x;
    MatArg dummy { nullptr, nullptr, nullptr };
    if (b < NB_ACC) {
        accum_block(b, x_title, g_bkt_ta, g_cnt_ta, CAP_TA, g_agg_ta, NL);
    } else if (b < NB_ACC + NB_TL) {
        MatArg y0 { label_embed, W_l_tl, nullptr };
        gemm_block<1, false, false>(b - NB_ACC, y0, dummy, nullptr,
            nullptr, nullptr, nullptr, 0, nullptr, nullptr, g_yl, NL, sAT, sW);
    } else {
        MatArg z0 { label_embed, W_l_ll, nullptr };
        gemm_block<1, false, false>(b - NB_ACC - NB_TL, z0, dummy, nullptr,
            nullptr, nullptr, nullptr, 0, nullptr, nullptr, g_zl, NL, sAT, sW);
    }
}

// ---------------- ta overflow cleanup (expected ~0 entries) ----------------
__global__ void __launch_bounds__(256) overflow_ta_kernel(const float* __restrict__ x)
{
    int w      = (int)((blockIdx.x * blockDim.x + threadIdx.x) >> 5);
    int nwarps = (int)((gridDim.x * blockDim.x) >> 5);
    int lane   = threadIdx.x & 31;
    int n = g_ovf_n[0];
    for (int idx = w; idx < n; idx += nwarps) {
        int2 e = g_ovf_ta[idx];
        float4 v = *((const float4*)(x + (size_t)e.x * DD) + lane);
        float* a = g_agg_ta + (size_t)e.y * DD + lane * 4;
        atomicAdd(a + 0, v.x);
        atomicAdd(a + 1, v.y);
        atomicAdd(a + 2, v.z);
        atomicAdd(a + 3, v.w);
    }
}

// ---------------- kernel B: out_label GEMM (long blocks first) + out_title GEMM ----------------
__global__ void __launch_bounds__(256) midB_kernel(
    const float* __restrict__ x_title, const float* __restrict__ label_embed,
    const float* __restrict__ W_r_tl,  const float* __restrict__ W_l_tl,
    const float* __restrict__ b_l_tl,
    float* __restrict__ out_title, float* __restrict__ out_label)
{
    __shared__ __align__(16) float sAT[32 * AT_STRIDE];
    __shared__ __align__(16) float sW[32][DD];
    int b = blockIdx.x;
    MatArg dummy { nullptr, nullptr, nullptr };
    if (b < NB_TL) {
        // out_label = relu( agg_ta/cnt @ W_l_tl^T + x_label @ Wsum^T + bsum
        //                   + mean over ll-bucket of ZL rows )   [2x work: schedule first]
        MatArg l0 { g_agg_ta, W_l_tl, g_cnt_ta };
        MatArg l1 { label_embed, g_Wsum, nullptr };
        gemm_block<2, true, true>(b, l0, l1, g_bsum,
            g_zl, g_bkt_ll, g_cnt_ll, CAP_LL, g_ovf_ll, &g_ovf_n[1],
            out_label, NL, sAT, sW);
    } else {
        // out_title = relu( x_title @ W_r_tl^T + b_l_tl + mean over rev-bucket of YL rows )
        MatArg t0 { x_title, W_r_tl, nullptr };
        gemm_block<1, true, true>(b - NB_TL, t0, dummy, b_l_tl,
            g_yl, g_bkt_rev, g_cnt_rev, CAP_REV, g_ovf_rev, &g_ovf_n[2],
            out_title, NT, sAT, sW);
    }
}

// ---------------- supervision-edge dot products: one warp per edge ----------------
__global__ void __launch_bounds__(256) pred_kernel(
    const float* __restrict__ ot, const float* __restrict__ ol,
    const int* __restrict__ es, const int* __restrict__ ed,
    float* __restrict__ pred, int E)
{
    int e    = (int)(((size_t)blockIdx.x * blockDim.x + threadIdx.x) >> 5);
    int lane = threadIdx.x & 31;
    if (e >= E) return;
    int s = es[e], d = ed[e];
    float4 a = *((const float4*)(ot + (size_t)s * DD) + lane);
    float4 b = *((const float4*)(ol + (size_t)d * DD) + lane);
    float v = a.x * b.x + a.y * b.y + a.z * b.z + a.w * b.w;
    #pragma unroll
    for (int o = 16; o > 0; o >>= 1) v += __shfl_xor_sync(0xffffffffu, v, o);
    if (lane == 0) pred[e] = v;
}

// ---------------- orchestration ----------------
extern "C" void kernel_launch(void* const* d_in, const int* in_sizes, int n_in,
                              void* d_out, int out_size)
{
    const float* x_title      = (const float*)d_in[0];
    const float* label_embed  = (const float*)d_in[1];   // == x_label (label_node_id is identity)
    const float* W_l_tl       = (const float*)d_in[2];
    const float* b_l_tl       = (const float*)d_in[3];
    const float* W_r_tl       = (const float*)d_in[4];
    const float* W_l_ll       = (const float*)d_in[5];
    const float* b_l_ll       = (const float*)d_in[6];
    const float* W_r_ll       = (const float*)d_in[7];
    const int* ta_src   = (const int*)d_in[9];
    const int* ta_dst   = (const int*)d_in[10];
    const int* rev_src  = (const int*)d_in[11];
    const int* rev_dst  = (const int*)d_in[12];
    const int* ll_src   = (const int*)d_in[13];
    const int* ll_dst   = (const int*)d_in[14];
    const int* el_src   = (const int*)d_in[15];
    const int* el_dst   = (const int*)d_in[16];

    float* out       = (float*)d_out;
    float* pred      = out;                                   // [ELBL]
    float* out_title = out + ELBL;                            // [NT, D]
    float* out_label = out + ELBL + (size_t)NT * DD;          // [NL, D]

    // setup: zero counters + fold Wsum/bsum
    setup_kernel<<<512, 256>>>(W_r_tl, W_r_ll, b_l_tl, b_l_ll);

    // pass 1: all bucket fills (one launch, 3 independent relations)
    fill_all_kernel<<<NB_FILL, 256>>>(
        ta_src, ta_dst, ll_src, ll_dst, rev_src, rev_dst);

    // kernel A: accum_ta (L2-bound) + YL + ZL transforms (FMA-bound), co-resident
    midA_kernel<<<NB_ACC + 2 * NB_TL, 256>>>(x_title, label_embed, W_l_tl, W_l_ll);

    // ta overflow cleanup (expected empty; exactness guarantee)
    overflow_ta_kernel<<<64, 256>>>(x_title);

    // kernel B: both output GEMMs with fused epilogue gathers (long blocks first)
    midB_kernel<<<NB_TT + NB_TL, 256>>>(
        x_title, label_embed, W_r_tl, W_l_tl, b_l_tl, out_title, out_label);

    // supervision-edge dot products
    pred_kernel<<<(int)(((size_t)ELBL * 32 + 255) / 256), 256>>>(
        out_title, out_label, el_src, el_dst, pred, ELBL);
}

// round 16
// speedup vs baseline: 1.0997x; 1.0055x over previous
#include <cuda_runtime.h>

typedef unsigned long long ull;

#define NT   200000
#define NL   50000
#define DD   128
#define ETA  1000000
#define EREV 1000000
#define ELL  500000
#define ELBL 500000

#define CAP_TA  64
#define CAP_LL  64
#define CAP_REV 32

#define NB_ACC   ((NL + 7) / 8)        // 6250 accum blocks (8 warps = 8 rows each)
#define NB_TL    ((NL + 63) / 64)      // 782 blocks per label-sized GEMM
#define NB_TT    ((NT + 63) / 64)      // 3125 blocks for title-sized GEMM
#define NB_FILL  ((ETA + ELL + EREV + 255) / 256)

// ---------------- scratch (device globals: no allocation allowed) ----------------
__device__ float g_agg_ta [(size_t)NL * DD];   // 25.6 MB
__device__ float g_yl     [(size_t)NL * DD];   // 25.6 MB  (YL = x_label @ W_l_tl^T)
__device__ float g_zl     [(size_t)NL * DD];   // 25.6 MB  (ZL = x_label @ W_l_ll^T)
__device__ int   g_cnt_rev[NT];
__device__ int   g_cnt_ta [NL];
__device__ int   g_cnt_ll [NL];
__device__ int   g_bkt_ta [(size_t)NL * CAP_TA];
__device__ int   g_bkt_ll [(size_t)NL * CAP_LL];
__device__ int   g_bkt_rev[(size_t)NT * CAP_REV];
__device__ int2  g_ovf_ta [ETA];               // capacity = E: always correct
__device__ int2  g_ovf_ll [ELL];
__device__ int2  g_ovf_rev[EREV];
__device__ int   g_ovf_n[3];                   // [0]=ta [1]=ll [2]=rev
__device__ float g_Wsum[DD * DD];
__device__ float g_bsum[DD];

// ---------------- packed f32x2 helpers (Blackwell FFMA2 path) ----------------
__device__ __forceinline__ ull pack2(float x, float y) {
    ull r; asm("mov.b64 %0, {%1, %2};" : "=l"(r) : "f"(x), "f"(y)); return r;
}
__device__ __forceinline__ void unpack2(float& x, float& y, ull v) {
    asm("mov.b64 {%0, %1}, %2;" : "=f"(x), "=f"(y) : "l"(v));
}
__device__ __forceinline__ void ffma2(ull& acc, ull a, ull b) {
    asm("fma.rn.f32x2 %0, %1, %2, %0;" : "+l"(acc) : "l"(a), "l"(b));
}

// ---------------- setup: zero counters + fold weights (one launch) ----------------
__global__ void setup_kernel(const float* __restrict__ wr1, const float* __restrict__ wr2,
                             const float* __restrict__ b1,  const float* __restrict__ b2) {
    int tid    = blockIdx.x * blockDim.x + threadIdx.x;
    int stride = gridDim.x * blockDim.x;
    for (int i = tid; i < NT; i += stride) g_cnt_rev[i] = 0;
    for (int i = tid; i < NL; i += stride) { g_cnt_ta[i] = 0; g_cnt_ll[i] = 0; }
    for (int i = tid; i < DD * DD; i += stride) g_Wsum[i] = wr1[i] + wr2[i];
    if (tid < DD) g_bsum[tid] = b1[tid] + b2[tid];
    if (tid < 3)  g_ovf_n[tid] = 0;
}

// ---------------- bucket fill ----------------
__device__ __forceinline__ void fill_one(
    int e, const int* __restrict__ src, const int* __restrict__ dst,
    int* __restrict__ cnt, int* __restrict__ bkt, int cap,
    int2* __restrict__ ovf, int* __restrict__ ovfn)
{
    int s = src[e];
    int d = dst[e];
    int pos = atomicAdd(&cnt[d], 1);
    if (pos < cap) {
        bkt[(size_t)d * cap + pos] = s;
    } else {
        int o = atomicAdd(ovfn, 1);
        ovf[o] = make_int2(s, d);
    }
}

__global__ void __launch_bounds__(256) fill_all_kernel(
    const int* __restrict__ ta_src,  const int* __restrict__ ta_dst,
    const int* __restrict__ ll_src,  const int* __restrict__ ll_dst,
    const int* __restrict__ rev_src, const int* __restrict__ rev_dst)
{
    int i = blockIdx.x * blockDim.x + threadIdx.x;
    if (i < ETA) {
        fill_one(i, ta_src, ta_dst, g_cnt_ta, g_bkt_ta, CAP_TA, g_ovf_ta, &g_ovf_n[0]);
    } else if (i < ETA + ELL) {
        fill_one(i - ETA, ll_src, ll_dst, g_cnt_ll, g_bkt_ll, CAP_LL, g_ovf_ll, &g_ovf_n[1]);
    } else if (i < ETA + ELL + EREV) {
        fill_one(i - ETA - ELL, rev_src, rev_dst, g_cnt_rev, g_bkt_rev, CAP_REV, g_ovf_rev, &g_ovf_n[2]);
    }
}

// ---------------- accumulate block body (1 warp per destination row) ----------------
__device__ __forceinline__ void accum_block(
    int bid, const float* __restrict__ x, const int* __restrict__ bkt,
    const int* __restrict__ cnt, int cap, float* __restrict__ agg, int N)
{
    int w    = bid * 8 + (threadIdx.x >> 5);
    int lane = threadIdx.x & 31;
    if (w >= N) return;
    int c = cnt[w];
    if (c > cap) c = cap;
    const int* b = bkt + (size_t)w * cap;
    float4 acc = make_float4(0.f, 0.f, 0.f, 0.f);
    int i = 0;
    for (; i + 4 <= c; i += 4) {
        int s0 = b[i], s1 = b[i + 1], s2 = b[i + 2], s3 = b[i + 3];
        float4 v0 = *((const float4*)(x + (size_t)s0 * DD) + lane);
        float4 v1 = *((const float4*)(x + (size_t)s1 * DD) + lane);
        float4 v2 = *((const float4*)(x + (size_t)s2 * DD) + lane);
        float4 v3 = *((const float4*)(x + (size_t)s3 * DD) + lane);
        acc.x += v0.x + v1.x + v2.x + v3.x;
        acc.y += v0.y + v1.y + v2.y + v3.y;
        acc.z += v0.z + v1.z + v2.z + v3.z;
        acc.w += v0.w + v1.w + v2.w + v3.w;
    }
    for (; i < c; i++) {
        int s = b[i];
        float4 v = *((const float4*)(x + (size_t)s * DD) + lane);
        acc.x += v.x; acc.y += v.y; acc.z += v.z; acc.w += v.w;
    }
    *((float4*)(agg + (size_t)w * DD) + lane) = acc;
}

// ---------------- GEMM block body (FFMA2 core + optional epilogue bucket-gather) ----------------
struct MatArg { const float* A; const float* W; const int* cnt; };

#define AT_STRIDE 66

template <int NM, bool RELU, bool GATHER>
__device__ __forceinline__ void gemm_block(
    int bid, MatArg m0, MatArg m1,
    const float* __restrict__ bias,
    const float* __restrict__ gY, const int* __restrict__ gbkt,
    const int* __restrict__ gcnt, int gcap,
    const int2* __restrict__ govf, const int* __restrict__ govfn,
    float* __restrict__ out, int nrows,
    float* sAT, float (*sW)[DD])
{
    const int t    = threadIdx.x;
    const int tx   = t & 31;
    const int ty   = t >> 5;
    const int row0 = bid * 64;
    const int col  = tx * 4;

    ull acc2[4][4];   // [row-pair][col]
    {
        float4 b = bias ? *(const float4*)(bias + col) : make_float4(0.f, 0.f, 0.f, 0.f);
        ull b0 = pack2(b.x, b.x), b1 = pack2(b.y, b.y);
        ull b2 = pack2(b.z, b.z), b3 = pack2(b.w, b.w);
        #pragma unroll
        for (int p = 0; p < 4; p++) {
            acc2[p][0] = b0; acc2[p][1] = b1; acc2[p][2] = b2; acc2[p][3] = b3;
        }
    }

    MatArg mats[2] = { m0, m1 };
    #pragma unroll
    for (int m = 0; m < NM; m++) {
        const float* __restrict__ A   = mats[m].A;
        const float* __restrict__ W   = mats[m].W;
        const int*   __restrict__ cnt = mats[m].cnt;
        for (int kc = 0; kc < 4; kc++) {
            __syncthreads();
            // --- load A tile, scaled, stored TRANSPOSED: sAT[k][row] ---
            #pragma unroll
            for (int i = 0; i < 2; i++) {
                int lin = (t + i * 256) * 4;
                int r   = lin >> 5;          // 0..63
                int kk  = lin & 31;
                int gr  = row0 + r;
                float4 v = make_float4(0.f, 0.f, 0.f, 0.f);
                float  s = 1.0f;
                if (gr < nrows) {
                    v = *(const float4*)(A + (size_t)gr * DD + kc * 32 + kk);
                    if (cnt) s = 1.0f / fmaxf((float)cnt[gr], 1.0f);
                }
                sAT[(kk + 0) * AT_STRIDE + r] = v.x * s;
                sAT[(kk + 1) * AT_STRIDE + r] = v.y * s;
                sAT[(kk + 2) * AT_STRIDE + r] = v.z * s;
                sAT[(kk + 3) * AT_STRIDE + r] = v.w * s;
            }
            // --- load W tile transposed: sW[k][col] ---
            {
                int c = t & 127, half = t >> 7;
                const float* Wp = W + c * DD + kc * 32 + half * 16;
                #pragma unroll
                for (int q = 0; q < 4; q++) {
                    float4 w = *(const float4*)(Wp + q * 4);
                    int kk = half * 16 + q * 4;
                    sW[kk + 0][c] = w.x; sW[kk + 1][c] = w.y;
                    sW[kk + 2][c] = w.z; sW[kk + 3][c] = w.w;
                }
            }
            __syncthreads();
            // --- inner product: 32 k-steps, 16 FFMA2 each ---
            #pragma unroll 4
            for (int k = 0; k < 32; k++) {
                const float* ap = &sAT[k * AT_STRIDE + ty * 8];
                ull a01 = *(const ull*)(ap + 0);
                ull a23 = *(const ull*)(ap + 2);
                ull a45 = *(const ull*)(ap + 4);
                ull a67 = *(const ull*)(ap + 6);
                float4 w = *(const float4*)&sW[k][col];
                ull w0 = pack2(w.x, w.x);
                ull w1 = pack2(w.y, w.y);
                ull w2 = pack2(w.z, w.z);
                ull w3 = pack2(w.w, w.w);
                ffma2(acc2[0][0], a01, w0); ffma2(acc2[0][1], a01, w1);
                ffma2(acc2[0][2], a01, w2); ffma2(acc2[0][3], a01, w3);
                ffma2(acc2[1][0], a23, w0); ffma2(acc2[1][1], a23, w1);
                ffma2(acc2[1][2], a23, w2); ffma2(acc2[1][3], a23, w3);
                ffma2(acc2[2][0], a45, w0); ffma2(acc2[2][1], a45, w1);
                ffma2(acc2[2][2], a45, w2); ffma2(acc2[2][3], a45, w3);
                ffma2(acc2[3][0], a67, w0); ffma2(acc2[3][1], a67, w1);
                ffma2(acc2[3][2], a67, w2); ffma2(acc2[3][3], a67, w3);
            }
        }
    }

    // epilogue: unpack, optional bucket-gather mean-add, relu, store
    int novf = 0;
    if (GATHER) novf = *govfn;   // hoisted: one load per thread, not per row

    #pragma unroll
    for (int p = 0; p < 4; p++) {
        int rlo = row0 + ty * 8 + 2 * p;
        float4 o2[2];
        unpack2(o2[0].x, o2[1].x, acc2[p][0]);
        unpack2(o2[0].y, o2[1].y, acc2[p][1]);
        unpack2(o2[0].z, o2[1].z, acc2[p][2]);
        unpack2(o2[0].w, o2[1].w, acc2[p][3]);
        #pragma unroll
        for (int h = 0; h < 2; h++) {
            int r = rlo + h;
            if (r >= nrows) continue;
            float4 o = o2[h];
            if (GATHER) {
                int c  = gcnt[r];
                int cc = c < gcap ? c : gcap;
                const int* b = gbkt + (size_t)r * gcap;
                float4 add = make_float4(0.f, 0.f, 0.f, 0.f);
                int i = 0;
                // 4-way batched: int4 index load + 4 independent float4 gathers (MLP=4)
                for (; i + 4 <= cc; i += 4) {
                    int4 s4 = *(const int4*)(b + i);
                    float4 v0 = *(const float4*)(gY + (size_t)s4.x * DD + col);
                    float4 v1 = *(const float4*)(gY + (size_t)s4.y * DD + col);
                    float4 v2 = *(const float4*)(gY + (size_t)s4.z * DD + col);
                    float4 v3 = *(const float4*)(gY + (size_t)s4.w * DD + col);
                    add.x += v0.x + v1.x + v2.x + v3.x;
                    add.y += v0.y + v1.y + v2.y + v3.y;
                    add.z += v0.z + v1.z + v2.z + v3.z;
                    add.w += v0.w + v1.w + v2.w + v3.w;
                }
                for (; i < cc; i++) {
                    int s = b[i];
                    float4 v = *(const float4*)(gY + (size_t)s * DD + col);
                    add.x += v.x; add.y += v.y; add.z += v.z; add.w += v.w;
                }
                if (novf > 0) {          // ~never taken; exact fallback
                    for (int j = 0; j < novf; j++) {
                        int2 e = govf[j];
                        if (e.y == r) {
                            float4 v = *(const float4*)(gY + (size_t)e.x * DD + col);
                            add.x += v.x; add.y += v.y; add.z += v.z; add.w += v.w;
                        }
                    }
                }
                float sc = 1.0f / fmaxf((float)c, 1.0f);
                o.x += add.x * sc; o.y += add.y * sc;
                o.z += add.z * sc; o.w += add.w * sc;
            }
            if (RELU) {
                o.x = fmaxf(o.x, 0.f); o.y = fmaxf(o.y, 0.f);
                o.z = fmaxf(o.z, 0.f); o.w = fmaxf(o.w, 0.f);
            }
            *(float4*)(out + (size_t)r * DD + col) = o;
        }
    }
}

// ---------------- kernel A: accum_ta + YL transform + ZL transform (co-launched) ----------------
__global__ void __launch_bounds__(256) midA_kernel(
    const float* __restrict__ x_title, const float* __restrict__ label_embed,
    const float* __restrict__ W_l_tl,  const float* __restrict__ W_l_ll)
{
    __shared__ __align__(16) float sAT[32 * AT_STRIDE];
    __shared__ __align__(16) float sW[32][DD];
    int b = blockIdx.x;
    MatArg dummy { nullptr, nullptr, nullptr };
    if (b < NB_ACC) {
        accum_block(b, x_title, g_bkt_ta, g_cnt_ta, CAP_TA, g_agg_ta, NL);
    } else if (b < NB_ACC + NB_TL) {
        MatArg y0 { label_embed, W_l_tl, nullptr };
        gemm_block<1, false, false>(b - NB_ACC, y0, dummy, nullptr,
            nullptr, nullptr, nullptr, 0, nullptr, nullptr, g_yl, NL, sAT, sW);
    } else {
        MatArg z0 { label_embed, W_l_ll, nullptr };
        gemm_block<1, false, false>(b - NB_ACC - NB_TL, z0, dummy, nullptr,
            nullptr, nullptr, nullptr, 0, nullptr, nullptr, g_zl, NL, sAT, sW);
    }
}

// ---------------- ta overflow cleanup (expected ~0 entries) ----------------
__global__ void __launch_bounds__(256) overflow_ta_kernel(const float* __restrict__ x)
{
    int w      = (int)((blockIdx.x * blockDim.x + threadIdx.x) >> 5);
    int nwarps = (int)((gridDim.x * blockDim.x) >> 5);
    int lane   = threadIdx.x & 31;
    int n = g_ovf_n[0];
    for (int idx = w; idx < n; idx += nwarps) {
        int2 e = g_ovf_ta[idx];
        float4 v = *((const float4*)(x + (size_t)e.x * DD) + lane);
        float* a = g_agg_ta + (size_t)e.y * DD + lane * 4;
        atomicAdd(a + 0, v.x);
        atomicAdd(a + 1, v.y);
        atomicAdd(a + 2, v.z);
        atomicAdd(a + 3, v.w);
    }
}

// ---------------- kernel B: out_title GEMM + out_label GEMM (co-launched) ----------------
__global__ void __launch_bounds__(256) midB_kernel(
    const float* __restrict__ x_title, const float* __restrict__ label_embed,
    const float* __restrict__ W_r_tl,  const float* __restrict__ W_l_tl,
    const float* __restrict__ b_l_tl,
    float* __restrict__ out_title, float* __restrict__ out_label)
{
    __shared__ __align__(16) float sAT[32 * AT_STRIDE];
    __shared__ __align__(16) float sW[32][DD];
    int b = blockIdx.x;
    MatArg dummy { nullptr, nullptr, nullptr };
    if (b < NB_TT) {
        // out_title = relu( x_title @ W_r_tl^T + b_l_tl + mean over rev-bucket of YL rows )
        MatArg t0 { x_title, W_r_tl, nullptr };
        gemm_block<1, true, true>(b, t0, dummy, b_l_tl,
            g_yl, g_bkt_rev, g_cnt_rev, CAP_REV, g_ovf_rev, &g_ovf_n[2],
            out_title, NT, sAT, sW);
    } else {
        // out_label = relu( agg_ta/cnt @ W_l_tl^T + x_label @ Wsum^T + bsum
        //                   + mean over ll-bucket of ZL rows )
        MatArg l0 { g_agg_ta, W_l_tl, g_cnt_ta };
        MatArg l1 { label_embed, g_Wsum, nullptr };
        gemm_block<2, true, true>(b - NB_TT, l0, l1, g_bsum,
            g_zl, g_bkt_ll, g_cnt_ll, CAP_LL, g_ovf_ll, &g_ovf_n[1],
            out_label, NL, sAT, sW);
    }
}

// ---------------- supervision-edge dot products: one warp per edge ----------------
__global__ void __launch_bounds__(256) pred_kernel(
    const float* __restrict__ ot, const float* __restrict__ ol,
    const int* __restrict__ es, const int* __restrict__ ed,
    float* __restrict__ pred, int E)
{
    int e    = (int)(((size_t)blockIdx.x * blockDim.x + threadIdx.x) >> 5);
    int lane = threadIdx.x & 31;
    if (e >= E) return;
    int s = es[e], d = ed[e];
    float4 a = *((const float4*)(ot + (size_t)s * DD) + lane);
    float4 b = *((const float4*)(ol + (size_t)d * DD) + lane);
    float v = a.x * b.x + a.y * b.y + a.z * b.z + a.w * b.w;
    #pragma unroll
    for (int o = 16; o > 0; o >>= 1) v += __shfl_xor_sync(0xffffffffu, v, o);
    if (lane == 0) pred[e] = v;
}

// ---------------- orchestration ----------------
extern "C" void kernel_launch(void* const* d_in, const int* in_sizes, int n_in,
                              void* d_out, int out_size)
{
    const float* x_title      = (const float*)d_in[0];
    const float* label_embed  = (const float*)d_in[1];   // == x_label (label_node_id is identity)
    const float* W_l_tl       = (const float*)d_in[2];
    const float* b_l_tl       = (const float*)d_in[3];
    const float* W_r_tl       = (const float*)d_in[4];
    const float* W_l_ll       = (const float*)d_in[5];
    const float* b_l_ll       = (const float*)d_in[6];
    const float* W_r_ll       = (const float*)d_in[7];
    const int* ta_src   = (const int*)d_in[9];
    const int* ta_dst   = (const int*)d_in[10];
    const int* rev_src  = (const int*)d_in[11];
    const int* rev_dst  = (const int*)d_in[12];
    const int* ll_src   = (const int*)d_in[13];
    const int* ll_dst   = (const int*)d_in[14];
    const int* el_src   = (const int*)d_in[15];
    const int* el_dst   = (const int*)d_in[16];

    float* out       = (float*)d_out;
    float* pred      = out;                                   // [ELBL]
    float* out_title = out + ELBL;                            // [NT, D]
    float* out_label = out + ELBL + (size_t)NT * DD;          // [NL, D]

    // setup: zero counters + fold Wsum/bsum
    setup_kernel<<<512, 256>>>(W_r_tl, W_r_ll, b_l_tl, b_l_ll);

    // pass 1: all bucket fills (one launch, 3 independent relations)
    fill_all_kernel<<<NB_FILL, 256>>>(
        ta_src, ta_dst, ll_src, ll_dst, rev_src, rev_dst);

    // kernel A: accum_ta (L2-bound) + YL + ZL transforms (FMA-bound), co-resident
    midA_kernel<<<NB_ACC + 2 * NB_TL, 256>>>(x_title, label_embed, W_l_tl, W_l_ll);

    // ta overflow cleanup (expected empty; exactness guarantee)
    overflow_ta_kernel<<<64, 256>>>(x_title);

    // kernel B: both output GEMMs with fused epilogue gathers
    midB_kernel<<<NB_TT + NB_TL, 256>>>(
        x_title, label_embed, W_r_tl, W_l_tl, b_l_tl, out_title, out_label);

    // supervision-edge dot products
    pred_kernel<<<(int)(((size_t)ELBL * 32 + 255) / 256), 256>>>(
        out_title, out_label, el_src, el_dst, pred, ELBL);
}

// round 17
// speedup vs baseline: 1.1099x; 1.0093x over previous
#include <cuda_runtime.h>

typedef unsigned long long ull;

#define NT   200000
#define NL   50000
#define DD   128
#define ETA  1000000
#define EREV 1000000
#define ELL  500000
#define ELBL 500000

#define CAP_TA  64
#define CAP_LL  64
#define CAP_REV 32

#define NB_ACC   ((NL + 7) / 8)        // 6250 accum blocks (8 warps = 8 rows each)
#define NB_TL    ((NL + 63) / 64)      // 782 blocks per label-sized GEMM
#define NB_TT    ((NT + 63) / 64)      // 3125 blocks for title-sized GEMM
#define NB_FILL  ((ETA + ELL + EREV + 255) / 256)

// ---------------- scratch (device globals: no allocation allowed) ----------------
__device__ float g_agg_ta [(size_t)NL * DD];   // 25.6 MB
__device__ float g_yl     [(size_t)NL * DD];   // 25.6 MB  (YL = x_label @ W_l_tl^T)
__device__ float g_zl     [(size_t)NL * DD];   // 25.6 MB  (ZL = x_label @ W_l_ll^T)
__device__ int   g_cnt_rev[NT];
__device__ int   g_cnt_ta [NL];
__device__ int   g_cnt_ll [NL];
__device__ int   g_bkt_ta [(size_t)NL * CAP_TA];
__device__ int   g_bkt_ll [(size_t)NL * CAP_LL];
__device__ int   g_bkt_rev[(size_t)NT * CAP_REV];
__device__ int2  g_ovf_ta [ETA];               // capacity = E: always correct
__device__ int2  g_ovf_ll [ELL];
__device__ int2  g_ovf_rev[EREV];
__device__ int   g_ovf_n[3];                   // [0]=ta [1]=ll [2]=rev
__device__ float g_Wsum[DD * DD];
__device__ float g_bsum[DD];

// ---------------- packed f32x2 helpers (Blackwell FFMA2 path) ----------------
__device__ __forceinline__ ull pack2(float x, float y) {
    ull r; asm("mov.b64 %0, {%1, %2};" : "=l"(r) : "f"(x), "f"(y)); return r;
}
__device__ __forceinline__ void unpack2(float& x, float& y, ull v) {
    asm("mov.b64 {%0, %1}, %2;" : "=f"(x), "=f"(y) : "l"(v));
}
__device__ __forceinline__ void ffma2(ull& acc, ull a, ull b) {
    asm("fma.rn.f32x2 %0, %1, %2, %0;" : "+l"(acc) : "l"(a), "l"(b));
}

// ---------------- setup: zero counters + fold weights (one launch) ----------------
__global__ void setup_kernel(const float* __restrict__ wr1, const float* __restrict__ wr2,
                             const float* __restrict__ b1,  const float* __restrict__ b2) {
    int tid    = blockIdx.x * blockDim.x + threadIdx.x;
    int stride = gridDim.x * blockDim.x;
    for (int i = tid; i < NT; i += stride) g_cnt_rev[i] = 0;
    for (int i = tid; i < NL; i += stride) { g_cnt_ta[i] = 0; g_cnt_ll[i] = 0; }
    for (int i = tid; i < DD * DD; i += stride) g_Wsum[i] = wr1[i] + wr2[i];
    if (tid < DD) g_bsum[tid] = b1[tid] + b2[tid];
    if (tid < 3)  g_ovf_n[tid] = 0;
}

// ---------------- bucket fill ----------------
__device__ __forceinline__ void fill_one(
    int e, const int* __restrict__ src, const int* __restrict__ dst,
    int* __restrict__ cnt, int* __restrict__ bkt, int cap,
    int2* __restrict__ ovf, int* __restrict__ ovfn)
{
    int s = src[e];
    int d = dst[e];
    int pos = atomicAdd(&cnt[d], 1);
    if (pos < cap) {
        bkt[(size_t)d * cap + pos] = s;
    } else {
        int o = atomicAdd(ovfn, 1);
        ovf[o] = make_int2(s, d);
    }
}

__global__ void __launch_bounds__(256) fill_all_kernel(
    const int* __restrict__ ta_src,  const int* __restrict__ ta_dst,
    const int* __restrict__ ll_src,  const int* __restrict__ ll_dst,
    const int* __restrict__ rev_src, const int* __restrict__ rev_dst)
{
    int i = blockIdx.x * blockDim.x + threadIdx.x;
    if (i < ETA) {
        fill_one(i, ta_src, ta_dst, g_cnt_ta, g_bkt_ta, CAP_TA, g_ovf_ta, &g_ovf_n[0]);
    } else if (i < ETA + ELL) {
        fill_one(i - ETA, ll_src, ll_dst, g_cnt_ll, g_bkt_ll, CAP_LL, g_ovf_ll, &g_ovf_n[1]);
    } else if (i < ETA + ELL + EREV) {
        fill_one(i - ETA - ELL, rev_src, rev_dst, g_cnt_rev, g_bkt_rev, CAP_REV, g_ovf_rev, &g_ovf_n[2]);
    }
}

// ---------------- accumulate block body (1 warp per destination row) ----------------
__device__ __forceinline__ void accum_block(
    int bid, const float* __restrict__ x, const int* __restrict__ bkt,
    const int* __restrict__ cnt, int cap, float* __restrict__ agg, int N)
{
    int w    = bid * 8 + (threadIdx.x >> 5);
    int lane = threadIdx.x & 31;
    if (w >= N) return;
    int c = cnt[w];
    if (c > cap) c = cap;
    const int* b = bkt + (size_t)w * cap;
    float4 acc = make_float4(0.f, 0.f, 0.f, 0.f);
    int i = 0;
    for (; i + 4 <= c; i += 4) {
        int s0 = b[i], s1 = b[i + 1], s2 = b[i + 2], s3 = b[i + 3];
        float4 v0 = *((const float4*)(x + (size_t)s0 * DD) + lane);
        float4 v1 = *((const float4*)(x + (size_t)s1 * DD) + lane);
        float4 v2 = *((const float4*)(x + (size_t)s2 * DD) + lane);
        float4 v3 = *((const float4*)(x + (size_t)s3 * DD) + lane);
        acc.x += v0.x + v1.x + v2.x + v3.x;
        acc.y += v0.y + v1.y + v2.y + v3.y;
        acc.z += v0.z + v1.z + v2.z + v3.z;
        acc.w += v0.w + v1.w + v2.w + v3.w;
    }
    for (; i < c; i++) {
        int s = b[i];
        float4 v = *((const float4*)(x + (size_t)s * DD) + lane);
        acc.x += v.x; acc.y += v.y; acc.z += v.z; acc.w += v.w;
    }
    *((float4*)(agg + (size_t)w * DD) + lane) = acc;
}

// ---------------- GEMM block body (FFMA2 core + optional epilogue bucket-gather) ----------------
// MatArg.xsrc/ovf/ovfn: optional overflow fold-in for aggregated A matrices —
// rows beyond bucket capacity are added during the A-tile load (exactness
// guarantee without a separate cleanup launch; novf==0 in practice).
struct MatArg {
    const float* A; const float* W; const int* cnt;
    const float* xsrc; const int2* ovf; const int* ovfn;
};

#define AT_STRIDE 66

template <int NM, bool RELU, bool GATHER>
__device__ __forceinline__ void gemm_block(
    int bid, MatArg m0, MatArg m1,
    const float* __restrict__ bias,
    const float* __restrict__ gY, const int* __restrict__ gbkt,
    const int* __restrict__ gcnt, int gcap,
    const int2* __restrict__ govf, const int* __restrict__ govfn,
    float* __restrict__ out, int nrows,
    float* sAT, float (*sW)[DD])
{
    const int t    = threadIdx.x;
    const int tx   = t & 31;
    const int ty   = t >> 5;
    const int row0 = bid * 64;
    const int col  = tx * 4;

    ull acc2[4][4];   // [row-pair][col]
    {
        float4 b = bias ? *(const float4*)(bias + col) : make_float4(0.f, 0.f, 0.f, 0.f);
        ull b0 = pack2(b.x, b.x), b1 = pack2(b.y, b.y);
        ull b2 = pack2(b.z, b.z), b3 = pack2(b.w, b.w);
        #pragma unroll
        for (int p = 0; p < 4; p++) {
            acc2[p][0] = b0; acc2[p][1] = b1; acc2[p][2] = b2; acc2[p][3] = b3;
        }
    }

    MatArg mats[2] = { m0, m1 };
    #pragma unroll
    for (int m = 0; m < NM; m++) {
        const float* __restrict__ A   = mats[m].A;
        const float* __restrict__ W   = mats[m].W;
        const int*   __restrict__ cnt = mats[m].cnt;
        const float* __restrict__ xsrc = mats[m].xsrc;
        int movf = (xsrc && mats[m].ovfn) ? *(mats[m].ovfn) : 0;
        const int2* __restrict__ movp = mats[m].ovf;
        for (int kc = 0; kc < 4; kc++) {
            __syncthreads();
            // --- load A tile, scaled, stored TRANSPOSED: sAT[k][row] ---
            #pragma unroll
            for (int i = 0; i < 2; i++) {
                int lin = (t + i * 256) * 4;
                int r   = lin >> 5;          // 0..63
                int kk  = lin & 31;
                int gr  = row0 + r;
                float4 v = make_float4(0.f, 0.f, 0.f, 0.f);
                float  s = 1.0f;
                if (gr < nrows) {
                    v = *(const float4*)(A + (size_t)gr * DD + kc * 32 + kk);
                    if (movf > 0) {      // ~never taken; exact overflow fold-in
                        for (int j = 0; j < movf; j++) {
                            int2 e = movp[j];
                            if (e.y == gr) {
                                float4 x4 = *(const float4*)(xsrc + (size_t)e.x * DD + kc * 32 + kk);
                                v.x += x4.x; v.y += x4.y; v.z += x4.z; v.w += x4.w;
                            }
                        }
                    }
                    if (cnt) s = 1.0f / fmaxf((float)cnt[gr], 1.0f);
                }
                sAT[(kk + 0) * AT_STRIDE + r] = v.x * s;
                sAT[(kk + 1) * AT_STRIDE + r] = v.y * s;
                sAT[(kk + 2) * AT_STRIDE + r] = v.z * s;
                sAT[(kk + 3) * AT_STRIDE + r] = v.w * s;
            }
            // --- load W tile transposed: sW[k][col] ---
            {
                int c = t & 127, half = t >> 7;
                const float* Wp = W + c * DD + kc * 32 + half * 16;
                #pragma unroll
                for (int q = 0; q < 4; q++) {
                    float4 w = *(const float4*)(Wp + q * 4);
                    int kk = half * 16 + q * 4;
                    sW[kk + 0][c] = w.x; sW[kk + 1][c] = w.y;
                    sW[kk + 2][c] = w.z; sW[kk + 3][c] = w.w;
                }
            }
            __syncthreads();
            // --- inner product: 32 k-steps, 16 FFMA2 each ---
            #pragma unroll 4
            for (int k = 0; k < 32; k++) {
                const float* ap = &sAT[k * AT_STRIDE + ty * 8];
                ull a01 = *(const ull*)(ap + 0);
                ull a23 = *(const ull*)(ap + 2);
                ull a45 = *(const ull*)(ap + 4);
                ull a67 = *(const ull*)(ap + 6);
                float4 w = *(const float4*)&sW[k][col];
                ull w0 = pack2(w.x, w.x);
                ull w1 = pack2(w.y, w.y);
                ull w2 = pack2(w.z, w.z);
                ull w3 = pack2(w.w, w.w);
                ffma2(acc2[0][0], a01, w0); ffma2(acc2[0][1], a01, w1);
                ffma2(acc2[0][2], a01, w2); ffma2(acc2[0][3], a01, w3);
                ffma2(acc2[1][0], a23, w0); ffma2(acc2[1][1], a23, w1);
                ffma2(acc2[1][2], a23, w2); ffma2(acc2[1][3], a23, w3);
                ffma2(acc2[2][0], a45, w0); ffma2(acc2[2][1], a45, w1);
                ffma2(acc2[2][2], a45, w2); ffma2(acc2[2][3], a45, w3);
                ffma2(acc2[3][0], a67, w0); ffma2(acc2[3][1], a67, w1);
                ffma2(acc2[3][2], a67, w2); ffma2(acc2[3][3], a67, w3);
            }
        }
    }

    // epilogue: unpack, optional bucket-gather mean-add, relu, store
    int novf = 0;
    if (GATHER) novf = *govfn;   // hoisted: one load per thread, not per row

    #pragma unroll
    for (int p = 0; p < 4; p++) {
        int rlo = row0 + ty * 8 + 2 * p;
        float4 o2[2];
        unpack2(o2[0].x, o2[1].x, acc2[p][0]);
        unpack2(o2[0].y, o2[1].y, acc2[p][1]);
        unpack2(o2[0].z, o2[1].z, acc2[p][2]);
        unpack2(o2[0].w, o2[1].w, acc2[p][3]);
        #pragma unroll
        for (int h = 0; h < 2; h++) {
            int r = rlo + h;
            if (r >= nrows) continue;
            float4 o = o2[h];
            if (GATHER) {
                int c  = gcnt[r];
                int cc = c < gcap ? c : gcap;
                const int* b = gbkt + (size_t)r * gcap;
                float4 add = make_float4(0.f, 0.f, 0.f, 0.f);
                int i = 0;
                // 4-way batched: int4 index load + 4 independent float4 gathers (MLP=4)
                for (; i + 4 <= cc; i += 4) {
                    int4 s4 = *(const int4*)(b + i);
                    float4 v0 = *(const float4*)(gY + (size_t)s4.x * DD + col);
                    float4 v1 = *(const float4*)(gY + (size_t)s4.y * DD + col);
                    float4 v2 = *(const float4*)(gY + (size_t)s4.z * DD + col);
                    float4 v3 = *(const float4*)(gY + (size_t)s4.w * DD + col);
                    add.x += v0.x + v1.x + v2.x + v3.x;
                    add.y += v0.y + v1.y + v2.y + v3.y;
                    add.z += v0.z + v1.z + v2.z + v3.z;
                    add.w += v0.w + v1.w + v2.w + v3.w;
                }
                for (; i < cc; i++) {
                    int s = b[i];
                    float4 v = *(const float4*)(gY + (size_t)s * DD + col);
                    add.x += v.x; add.y += v.y; add.z += v.z; add.w += v.w;
                }
                if (novf > 0) {          // ~never taken; exact fallback
                    for (int j = 0; j < novf; j++) {
                        int2 e = govf[j];
                        if (e.y == r) {
                            float4 v = *(const float4*)(gY + (size_t)e.x * DD + col);
                            add.x += v.x; add.y += v.y; add.z += v.z; add.w += v.w;
                        }
                    }
                }
                float sc = 1.0f / fmaxf((float)c, 1.0f);
                o.x += add.x * sc; o.y += add.y * sc;
                o.z += add.z * sc; o.w += add.w * sc;
            }
            if (RELU) {
                o.x = fmaxf(o.x, 0.f); o.y = fmaxf(o.y, 0.f);
                o.z = fmaxf(o.z, 0.f); o.w = fmaxf(o.w, 0.f);
            }
            *(float4*)(out + (size_t)r * DD + col) = o;
        }
    }
}

// ---------------- kernel A: accum_ta + YL transform + ZL transform (co-launched) ----------------
__global__ void __launch_bounds__(256) midA_kernel(
    const float* __restrict__ x_title, const float* __restrict__ label_embed,
    const float* __restrict__ W_l_tl,  const float* __restrict__ W_l_ll)
{
    __shared__ __align__(16) float sAT[32 * AT_STRIDE];
    __shared__ __align__(16) float sW[32][DD];
    int b = blockIdx.x;
    MatArg dummy { nullptr, nullptr, nullptr, nullptr, nullptr, nullptr };
    if (b < NB_ACC) {
        accum_block(b, x_title, g_bkt_ta, g_cnt_ta, CAP_TA, g_agg_ta, NL);
    } else if (b < NB_ACC + NB_TL) {
        MatArg y0 { label_embed, W_l_tl, nullptr, nullptr, nullptr, nullptr };
        gemm_block<1, false, false>(b - NB_ACC, y0, dummy, nullptr,
            nullptr, nullptr, nullptr, 0, nullptr, nullptr, g_yl, NL, sAT, sW);
    } else {
        MatArg z0 { label_embed, W_l_ll, nullptr, nullptr, nullptr, nullptr };
        gemm_block<1, false, false>(b - NB_ACC - NB_TL, z0, dummy, nullptr,
            nullptr, nullptr, nullptr, 0, nullptr, nullptr, g_zl, NL, sAT, sW);
    }
}

// ---------------- kernel B: out_title GEMM + out_label GEMM (co-launched) ----------------
__global__ void __launch_bounds__(256) midB_kernel(
    const float* __restrict__ x_title, const float* __restrict__ label_embed,
    const float* __restrict__ W_r_tl,  const float* __restrict__ W_l_tl,
    const float* __restrict__ b_l_tl,
    float* __restrict__ out_title, float* __restrict__ out_label)
{
    __shared__ __align__(16) float sAT[32 * AT_STRIDE];
    __shared__ __align__(16) float sW[32][DD];
    int b = blockIdx.x;
    MatArg dummy { nullptr, nullptr, nullptr, nullptr, nullptr, nullptr };
    if (b < NB_TT) {
        // out_title = relu( x_title @ W_r_tl^T + b_l_tl + mean over rev-bucket of YL rows )
        MatArg t0 { x_title, W_r_tl, nullptr, nullptr, nullptr, nullptr };
        gemm_block<1, true, true>(b, t0, dummy, b_l_tl,
            g_yl, g_bkt_rev, g_cnt_rev, CAP_REV, g_ovf_rev, &g_ovf_n[2],
            out_title, NT, sAT, sW);
    } else {
        // out_label = relu( (agg_ta + ta-overflow)/cnt @ W_l_tl^T + x_label @ Wsum^T
        //                   + bsum + mean over ll-bucket of ZL rows )
        MatArg l0 { g_agg_ta, W_l_tl, g_cnt_ta, x_title, g_ovf_ta, &g_ovf_n[0] };
        MatArg l1 { label_embed, g_Wsum, nullptr, nullptr, nullptr, nullptr };
        gemm_block<2, true, true>(b - NB_TT, l0, l1, g_bsum,
            g_zl, g_bkt_ll, g_cnt_ll, CAP_LL, g_ovf_ll, &g_ovf_n[1],
            out_label, NL, sAT, sW);
    }
}

// ---------------- supervision-edge dot products: one warp per edge ----------------
__global__ void __launch_bounds__(256) pred_kernel(
    const float* __restrict__ ot, const float* __restrict__ ol,
    const int* __restrict__ es, const int* __restrict__ ed,
    float* __restrict__ pred, int E)
{
    int e    = (int)(((size_t)blockIdx.x * blockDim.x + threadIdx.x) >> 5);
    int lane = threadIdx.x & 31;
    if (e >= E) return;
    int s = es[e], d = ed[e];
    float4 a = *((const float4*)(ot + (size_t)s * DD) + lane);
    float4 b = *((const float4*)(ol + (size_t)d * DD) + lane);
    float v = a.x * b.x + a.y * b.y + a.z * b.z + a.w * b.w;
    #pragma unroll
    for (int o = 16; o > 0; o >>= 1) v += __shfl_xor_sync(0xffffffffu, v, o);
    if (lane == 0) pred[e] = v;
}

// ---------------- orchestration ----------------
extern "C" void kernel_launch(void* const* d_in, const int* in_sizes, int n_in,
                              void* d_out, int out_size)
{
    const float* x_title      = (const float*)d_in[0];
    const float* label_embed  = (const float*)d_in[1];   // == x_label (label_node_id is identity)
    const float* W_l_tl       = (const float*)d_in[2];
    const float* b_l_tl       = (const float*)d_in[3];
    const float* W_r_tl       = (const float*)d_in[4];
    const float* W_l_ll       = (const float*)d_in[5];
    const float* b_l_ll       = (const float*)d_in[6];
    const float* W_r_ll       = (const float*)d_in[7];
    const int* ta_src   = (const int*)d_in[9];
    const int* ta_dst   = (const int*)d_in[10];
    const int* rev_src  = (const int*)d_in[11];
    const int* rev_dst  = (const int*)d_in[12];
    const int* ll_src   = (const int*)d_in[13];
    const int* ll_dst   = (const int*)d_in[14];
    const int* el_src   = (const int*)d_in[15];
    const int* el_dst   = (const int*)d_in[16];

    float* out       = (float*)d_out;
    float* pred      = out;                                   // [ELBL]
    float* out_title = out + ELBL;                            // [NT, D]
    float* out_label = out + ELBL + (size_t)NT * DD;          // [NL, D]

    // setup: zero counters + fold Wsum/bsum
    setup_kernel<<<512, 256>>>(W_r_tl, W_r_ll, b_l_tl, b_l_ll);

    // pass 1: all bucket fills (one launch, 3 independent relations)
    fill_all_kernel<<<NB_FILL, 256>>>(
        ta_src, ta_dst, ll_src, ll_dst, rev_src, rev_dst);

    // kernel A: accum_ta (L2-bound) + YL + ZL transforms (FMA-bound), co-resident
    midA_kernel<<<NB_ACC + 2 * NB_TL, 256>>>(x_title, label_embed, W_l_tl, W_l_ll);

    // kernel B: both output GEMMs with fused epilogue gathers
    // (ta-overflow folded into out_label's A-tile load — no cleanup launch)
    midB_kernel<<<NB_TT + NB_TL, 256>>>(
        x_title, label_embed, W_r_tl, W_l_tl, b_l_tl, out_title, out_label);

    // supervision-edge dot products
    pred_kernel<<<(int)(((size_t)ELBL * 32 + 255) / 256), 256>>>(
        out_title, out_label, el_src, el_dst, pred, ELBL);
}